// round 3
// baseline (speedup 1.0000x reference)
#include <cuda_runtime.h>
#include <stdint.h>

// CRY gate, DIM=2, N=24, C=0 (bit 23), T=1 (bit 22), J-1=0, K-1=1, B=2.
// x_real/x_imag: (D=2^24, B=2) float32 row-major; out: (2, D, B) float32.
//
// Row layout in float4 units (2 rows x 2 batch per float4), per plane:
//   f4 index v in [0, 2^23). bit22 of v = control, bit21 = target.
//   control=0  (v < 2^22): identity copy.
//   control=1: pair (v, v+2^21) rotated by [[c,-s],[-s,c]], c=cos(th/2), s=sin(th/2).
//
// R2: uniform 64B-read/64B-write per thread, 4 independent LDG.128 each,
// to raise MLP in the copy half and equalize per-thread work.

static constexpr uint32_t N_F4_PER_PLANE = 1u << 23; // D*B/4
static constexpr uint32_t COPY_F4        = 1u << 22; // control=0 f4 count per plane
static constexpr uint32_t HALF           = 1u << 21;
static constexpr uint32_t TOTAL_THREADS  = 1u << 22; // 2^21 copy + 2^21 pair

__global__ void __launch_bounds__(256)
cry_kernel(const float4* __restrict__ xr,
           const float4* __restrict__ xi,
           const float*  __restrict__ angle,
           float4* __restrict__ outr,
           float4* __restrict__ outi)
{
    uint32_t tid = blockIdx.x * blockDim.x + threadIdx.x;

    if (tid < HALF) {
        // Copy region: this thread moves f4 slots {tid, tid+2^21} in both planes.
        uint32_t a = tid, b = tid + HALF;
        float4 ra = xr[a], rb = xr[b];
        float4 ia = xi[a], ib = xi[b];
        outr[a] = ra; outr[b] = rb;
        outi[a] = ia; outi[b] = ib;
    } else {
        // Pair region: control=1. p in [0, 2^21).
        uint32_t p  = tid - HALF;
        uint32_t v0 = COPY_F4 + p;      // target=0 member
        uint32_t v1 = v0 + HALF;        // target=1 partner

        float4 r0 = xr[v0], r1 = xr[v1];
        float4 i0 = xi[v0], i1 = xi[v1];

        float s, c;
        sincosf(angle[0] * 0.5f, &s, &c);

        float4 or0, or1, oi0, oi1;
        or0.x =  c * r0.x - s * r1.x;  or1.x = -s * r0.x + c * r1.x;
        or0.y =  c * r0.y - s * r1.y;  or1.y = -s * r0.y + c * r1.y;
        or0.z =  c * r0.z - s * r1.z;  or1.z = -s * r0.z + c * r1.z;
        or0.w =  c * r0.w - s * r1.w;  or1.w = -s * r0.w + c * r1.w;

        oi0.x =  c * i0.x - s * i1.x;  oi1.x = -s * i0.x + c * i1.x;
        oi0.y =  c * i0.y - s * i1.y;  oi1.y = -s * i0.y + c * i1.y;
        oi0.z =  c * i0.z - s * i1.z;  oi1.z = -s * i0.z + c * i1.z;
        oi0.w =  c * i0.w - s * i1.w;  oi1.w = -s * i0.w + c * i1.w;

        outr[v0] = or0; outr[v1] = or1;
        outi[v0] = oi0; outi[v1] = oi1;
    }
}

extern "C" void kernel_launch(void* const* d_in, const int* in_sizes, int n_in,
                              void* d_out, int out_size)
{
    const float4* xr    = (const float4*)d_in[0];
    const float4* xi    = (const float4*)d_in[1];
    const float*  angle = (const float*)d_in[2];

    float4* outr = (float4*)d_out;
    float4* outi = outr + N_F4_PER_PLANE;

    const int threads = 256;
    const int blocks  = (int)(TOTAL_THREADS / threads); // 16384
    cry_kernel<<<blocks, threads>>>(xr, xi, angle, outr, outi);
}

// round 4
// speedup vs baseline: 1.0059x; 1.0059x over previous
#include <cuda_runtime.h>
#include <stdint.h>

// CRY gate, DIM=2, N=24, C=0 (bit 23), T=1 (bit 22), J-1=0, K-1=1, B=2.
// x_real/x_imag: (D=2^24, B=2) float32 row-major; out: (2, D, B) float32.
//
// f4 index v in [0, 2^23) per plane; bit22 = control, bit21 = target.
//   control=0 (v < 2^22): identity copy.
//   control=1: pair (v, v+2^21) rotated by [[c,-s],[-s,c]],
//              c=cos(theta/2), s=sin(theta/2), same for real & imag planes.
//
// R3: R1 thread structure (best measured DRAM%) + streaming cache hints
// (.cs evict-first on all loads/stores) — zero-reuse 512MB stream should
// not churn L2 replacement state.

static constexpr uint32_t N_F4_PER_PLANE = 1u << 23; // D*B/4
static constexpr uint32_t COPY_F4        = 1u << 22; // control=0 region (per plane)
static constexpr uint32_t PAIR_F4        = 1u << 21; // control=1,target=0 region
static constexpr uint32_t TOTAL_THREADS  = COPY_F4 + PAIR_F4; // 6,291,456

__global__ void __launch_bounds__(256)
cry_kernel(const float4* __restrict__ xr,
           const float4* __restrict__ xi,
           const float*  __restrict__ angle,
           float4* __restrict__ outr,
           float4* __restrict__ outi)
{
    uint32_t tid = blockIdx.x * blockDim.x + threadIdx.x;
    if (tid >= TOTAL_THREADS) return;

    if (tid < COPY_F4) {
        // control = 0: identity copy, streaming
        float4 r = __ldcs(&xr[tid]);
        float4 i = __ldcs(&xi[tid]);
        __stcs(&outr[tid], r);
        __stcs(&outi[tid], i);
    } else {
        // control = 1: this thread owns the target=0 member of the pair
        uint32_t v0 = tid;             // in [2^22, 2^22 + 2^21)
        uint32_t v1 = tid + PAIR_F4;   // target=1 partner (+2^22 rows)

        float s, c;
        sincosf(angle[0] * 0.5f, &s, &c);

        float4 r0 = __ldcs(&xr[v0]), r1 = __ldcs(&xr[v1]);
        float4 i0 = __ldcs(&xi[v0]), i1 = __ldcs(&xi[v1]);

        float4 or0, or1, oi0, oi1;
        or0.x =  c * r0.x - s * r1.x;  or1.x = -s * r0.x + c * r1.x;
        or0.y =  c * r0.y - s * r1.y;  or1.y = -s * r0.y + c * r1.y;
        or0.z =  c * r0.z - s * r1.z;  or1.z = -s * r0.z + c * r1.z;
        or0.w =  c * r0.w - s * r1.w;  or1.w = -s * r0.w + c * r1.w;

        oi0.x =  c * i0.x - s * i1.x;  oi1.x = -s * i0.x + c * i1.x;
        oi0.y =  c * i0.y - s * i1.y;  oi1.y = -s * i0.y + c * i1.y;
        oi0.z =  c * i0.z - s * i1.z;  oi1.z = -s * i0.z + c * i1.z;
        oi0.w =  c * i0.w - s * i1.w;  oi1.w = -s * i0.w + c * i1.w;

        __stcs(&outr[v0], or0); __stcs(&outr[v1], or1);
        __stcs(&outi[v0], oi0); __stcs(&outi[v1], oi1);
    }
}

extern "C" void kernel_launch(void* const* d_in, const int* in_sizes, int n_in,
                              void* d_out, int out_size)
{
    const float4* xr    = (const float4*)d_in[0];
    const float4* xi    = (const float4*)d_in[1];
    const float*  angle = (const float*)d_in[2];

    float4* outr = (float4*)d_out;
    float4* outi = outr + N_F4_PER_PLANE;

    const int threads = 256;
    const int blocks  = (int)((TOTAL_THREADS + threads - 1) / threads); // 24576
    cry_kernel<<<blocks, threads>>>(xr, xi, angle, outr, outi);
}